// round 5
// baseline (speedup 1.0000x reference)
#include <cuda_runtime.h>
#include <cuda_bf16.h>
#include <cstdint>

// ---------------- problem constants ----------------
#define NROWS   8192
#define DDIM    256
#define HALF_N  4096

// ---------------- tiling ----------------
#define TM      128                   // rows per CTA
#define TN      64                    // cols per B tile
#define CS      2                     // column splits
#define COLS_PER_CTA (NROWS / CS)     // 4096
#define NTILES  (COLS_PER_CTA / TN)   // 64

// fp8 rows: 256 bytes, padded stride 272B (17 words*4... 68 words -> conflict-free phases)
#define ROWB    272
#define SA_BYTES (TM * ROWB)          // 34816
#define SB_BYTES (TN * ROWB)          // 17408
#define SUMS_OFF (SA_BYTES + 2 * SB_BYTES)
#define SMEM_BYTES (SUMS_OFF + TM * 2 * (int)sizeof(float))

// exp(2*c) = 2^(c * 2*log2(e))
#define TWO_LOG2E 2.8853900817779268f

// ---------------- device scratch ----------------
__device__ __align__(16) uint8_t g_z8[NROWS * DDIM];   // e4m3 normalized rows
__device__ float g_pos[NROWS];
__device__ float g_S[NROWS * CS];

// ---------------- helpers ----------------
__device__ __forceinline__ void cp16(void* dst_smem, const void* src_gmem) {
    uint32_t d = (uint32_t)__cvta_generic_to_shared(dst_smem);
    asm volatile("cp.async.cg.shared.global [%0], [%1], 16;" :: "r"(d), "l"(src_gmem));
}
// pack two floats -> e4m3x2 (lo in low byte, hi in high byte)
__device__ __forceinline__ uint16_t f2e4m3x2(float lo, float hi) {
    uint16_t h;
    asm("cvt.rn.satfinite.e4m3x2.f32 %0, %1, %2;" : "=h"(h) : "f"(hi), "f"(lo));
    return h;
}

// ---------------- kernel 1: fused normalize (fp32->e4m3) + exact positives ----
// one warp per pair (r, r+HALF_N); lane owns 8 consecutive features
__global__ __launch_bounds__(256) void k_norm_pos(const float* __restrict__ zi,
                                                  const float* __restrict__ zj) {
    int warp = threadIdx.x >> 5, lane = threadIdx.x & 31;
    int p = blockIdx.x * 8 + warp;                 // pair index 0..HALF_N-1
    const float4* si = (const float4*)(zi + (size_t)p * DDIM);
    const float4* sj = (const float4*)(zj + (size_t)p * DDIM);
    float4 a0 = si[lane * 2], a1 = si[lane * 2 + 1];
    float4 b0 = sj[lane * 2], b1 = sj[lane * 2 + 1];

    float ssi = a0.x*a0.x + a0.y*a0.y + a0.z*a0.z + a0.w*a0.w
              + a1.x*a1.x + a1.y*a1.y + a1.z*a1.z + a1.w*a1.w;
    float ssj = b0.x*b0.x + b0.y*b0.y + b0.z*b0.z + b0.w*b0.w
              + b1.x*b1.x + b1.y*b1.y + b1.z*b1.z + b1.w*b1.w;
    float dot = a0.x*b0.x + a0.y*b0.y + a0.z*b0.z + a0.w*b0.w
              + a1.x*b1.x + a1.y*b1.y + a1.z*b1.z + a1.w*b1.w;
#pragma unroll
    for (int o = 16; o; o >>= 1) {
        ssi += __shfl_xor_sync(0xffffffffu, ssi, o);
        ssj += __shfl_xor_sync(0xffffffffu, ssj, o);
        dot += __shfl_xor_sync(0xffffffffu, dot, o);
    }
    float ni = fmaxf(sqrtf(ssi), 1e-8f);
    float nj = fmaxf(sqrtf(ssj), 1e-8f);
    float sci = 1.0f / ni, scj = 1.0f / nj;

    if (lane == 0) {
        float pos = 2.0f * dot * sci * scj;        // logit of the positive pair
        g_pos[p] = pos;
        g_pos[p + HALF_N] = pos;
    }

    // emit e4m3 rows (8 bytes per lane)
    uint16_t h0 = f2e4m3x2(a0.x * sci, a0.y * sci);
    uint16_t h1 = f2e4m3x2(a0.z * sci, a0.w * sci);
    uint16_t h2 = f2e4m3x2(a1.x * sci, a1.y * sci);
    uint16_t h3 = f2e4m3x2(a1.z * sci, a1.w * sci);
    uint2 wa = { (uint32_t)h0 | ((uint32_t)h1 << 16),
                 (uint32_t)h2 | ((uint32_t)h3 << 16) };
    reinterpret_cast<uint2*>(g_z8 + (size_t)p * DDIM)[lane] = wa;

    h0 = f2e4m3x2(b0.x * scj, b0.y * scj);
    h1 = f2e4m3x2(b0.z * scj, b0.w * scj);
    h2 = f2e4m3x2(b1.x * scj, b1.y * scj);
    h3 = f2e4m3x2(b1.z * scj, b1.w * scj);
    uint2 wb = { (uint32_t)h0 | ((uint32_t)h1 << 16),
                 (uint32_t)h2 | ((uint32_t)h3 << 16) };
    reinterpret_cast<uint2*>(g_z8 + (size_t)(p + HALF_N) * DDIM)[lane] = wb;
}

// ---------------- kernel 2: fp8 fused GEMM + sum-exp ----------------
__global__ __launch_bounds__(256, 1) void k_gemm_lse() {
    extern __shared__ char smem[];
    uint8_t* sA  = (uint8_t*)smem;
    uint8_t* sB0 = (uint8_t*)(smem + SA_BYTES);
    uint8_t* sB1 = (uint8_t*)(smem + SA_BYTES + SB_BYTES);
    float* sums = (float*)(smem + SUMS_OFF);

    int tid = threadIdx.x;
    int lane = tid & 31, warp = tid >> 5;
    int wm = warp >> 1, wn = warp & 1;           // 4x2 warp grid, warp tile 32x32
    int cs = blockIdx.x, rt = blockIdx.y;
    int row0 = rt * TM, colBase = cs * COLS_PER_CTA;

    // stage A panel (128 rows x 256B), 16B chunks: 8 per thread
#pragma unroll
    for (int i = 0; i < 8; i++) {
        int id = i * 256 + tid;
        int rowl = id >> 4, ch = id & 15;
        cp16(sA + rowl * ROWB + ch * 16,
             g_z8 + (size_t)(row0 + rowl) * DDIM + ch * 16);
    }
    // stage B tile 0 (64 rows x 256B): 4 per thread
#pragma unroll
    for (int i = 0; i < 4; i++) {
        int id = i * 256 + tid;
        int rowl = id >> 4, ch = id & 15;
        cp16(sB0 + rowl * ROWB + ch * 16,
             g_z8 + (size_t)(colBase + rowl) * DDIM + ch * 16);
    }
    asm volatile("cp.async.commit_group;");

    uint32_t sA32 = (uint32_t)__cvta_generic_to_shared(sA);
    uint32_t sB32[2] = {(uint32_t)__cvta_generic_to_shared(sB0),
                        (uint32_t)__cvta_generic_to_shared(sB1)};

    // ldmatrix lane bases (byte addressing; fp8 m16n8k32 frag == bf16 k16 frag bytes)
    uint32_t aAddr[2];
#pragma unroll
    for (int mt = 0; mt < 2; mt++)
        aAddr[mt] = sA32 + (uint32_t)((wm * 32 + mt * 16 + (lane & 15)) * ROWB
                                      + (lane >> 4) * 16);
    uint32_t bOff[2];
#pragma unroll
    for (int p = 0; p < 2; p++)
        bOff[p] = (uint32_t)((wn * 32 + p * 16 + ((lane >> 4) << 3) + (lane & 7)) * ROWB
                             + ((lane >> 3) & 1) * 16);

    float rs[2][2] = {{0.f, 0.f}, {0.f, 0.f}};   // per-thread row sums (4 rows)

    for (int ct = 0; ct < NTILES; ct++) {
        int buf = ct & 1;
        if (ct + 1 < NTILES) {
            uint8_t* dstB = (ct & 1) ? sB0 : sB1;   // buffer (ct+1)&1
            int gcol0 = colBase + (ct + 1) * TN;
#pragma unroll
            for (int i = 0; i < 4; i++) {
                int id = i * 256 + tid;
                int rowl = id >> 4, ch = id & 15;
                cp16(dstB + rowl * ROWB + ch * 16,
                     g_z8 + (size_t)(gcol0 + rowl) * DDIM + ch * 16);
            }
            asm volatile("cp.async.commit_group;");
            asm volatile("cp.async.wait_group 1;");
        } else {
            asm volatile("cp.async.wait_group 0;");
        }
        __syncthreads();

        float c[2][4][4];
#pragma unroll
        for (int mt = 0; mt < 2; mt++)
#pragma unroll
            for (int nt = 0; nt < 4; nt++)
#pragma unroll
                for (int e = 0; e < 4; e++) c[mt][nt][e] = 0.f;

        uint32_t bBase = sB32[buf];
#pragma unroll
        for (int ks = 0; ks < 8; ks++) {            // 8 k-steps of 32 fp8
            uint32_t a[2][4];
#pragma unroll
            for (int mt = 0; mt < 2; mt++) {
                uint32_t addr = aAddr[mt] + ks * 32;
                asm volatile("ldmatrix.sync.aligned.m8n8.x4.shared.b16 {%0,%1,%2,%3}, [%4];"
                             : "=r"(a[mt][0]), "=r"(a[mt][1]), "=r"(a[mt][2]), "=r"(a[mt][3])
                             : "r"(addr));
            }
            uint32_t b[4][2];
#pragma unroll
            for (int p = 0; p < 2; p++) {
                uint32_t addr = bBase + bOff[p] + ks * 32;
                asm volatile("ldmatrix.sync.aligned.m8n8.x4.shared.b16 {%0,%1,%2,%3}, [%4];"
                             : "=r"(b[2*p][0]), "=r"(b[2*p][1]), "=r"(b[2*p+1][0]), "=r"(b[2*p+1][1])
                             : "r"(addr));
            }
#pragma unroll
            for (int mt = 0; mt < 2; mt++)
#pragma unroll
                for (int nt = 0; nt < 4; nt++)
                    asm volatile("mma.sync.aligned.m16n8k32.row.col.f32.e4m3.e4m3.f32 "
                                 "{%0,%1,%2,%3}, {%4,%5,%6,%7}, {%8,%9}, {%0,%1,%2,%3};"
                                 : "+f"(c[mt][nt][0]), "+f"(c[mt][nt][1]),
                                   "+f"(c[mt][nt][2]), "+f"(c[mt][nt][3])
                                 : "r"(a[mt][0]), "r"(a[mt][1]), "r"(a[mt][2]), "r"(a[mt][3]),
                                   "r"(b[nt][0]), "r"(b[nt][1]));
        }

        // epilogue: exp, diagonal mask, row accumulate (pos handled exactly elsewhere)
        int gcol0 = colBase + ct * TN;
#pragma unroll
        for (int mt = 0; mt < 2; mt++) {
#pragma unroll
            for (int hi = 0; hi < 2; hi++) {
                int i = row0 + wm * 32 + mt * 16 + (lane >> 2) + hi * 8;
                float acc = 0.f;
#pragma unroll
                for (int nt = 0; nt < 4; nt++) {
#pragma unroll
                    for (int lo = 0; lo < 2; lo++) {
                        float cv = c[mt][nt][hi * 2 + lo];
                        int j = gcol0 + wn * 32 + nt * 8 + ((lane & 3) << 1) + lo;
                        float ev;
                        asm("ex2.approx.f32 %0, %1;" : "=f"(ev) : "f"(cv * TWO_LOG2E));
                        if (j == i) ev = 0.f;              // mask self-diagonal
                        acc += ev;
                    }
                }
                rs[mt][hi] += acc;
            }
        }
        __syncthreads();   // protect smem buffers before next prefetch overwrites
    }

    // reduce per-row sums: quad shuffle, then combine the two wn warps via smem
#pragma unroll
    for (int mt = 0; mt < 2; mt++)
#pragma unroll
        for (int hi = 0; hi < 2; hi++) {
            float v = rs[mt][hi];
            v += __shfl_xor_sync(0xffffffffu, v, 1);
            v += __shfl_xor_sync(0xffffffffu, v, 2);
            if ((lane & 3) == 0) {
                int rl = wm * 32 + mt * 16 + (lane >> 2) + hi * 8;
                sums[rl * 2 + wn] = v;
            }
        }
    __syncthreads();
    if (tid < TM) {
        float S = sums[tid * 2] + sums[tid * 2 + 1];
        g_S[(size_t)(row0 + tid) * CS + cs] = S;
    }
}

// ---------------- kernel 3: deterministic final reduction ----------------
__global__ __launch_bounds__(256) void k_finalize(float* __restrict__ out) {
    __shared__ float red[256];
    int tid = threadIdx.x;
    float acc = 0.f;
    for (int r = tid; r < NROWS; r += 256) {
        float S = g_S[r * CS] + g_S[r * CS + 1];
        acc += logf(S) - g_pos[r];
    }
    red[tid] = acc;
    __syncthreads();
#pragma unroll
    for (int s = 128; s > 0; s >>= 1) {
        if (tid < s) red[tid] += red[tid + s];
        __syncthreads();
    }
    if (tid == 0) out[0] = red[0] * (1.0f / (float)NROWS);
}

// ---------------- launcher ----------------
extern "C" void kernel_launch(void* const* d_in, const int* in_sizes, int n_in,
                              void* d_out, int out_size) {
    (void)in_sizes; (void)n_in; (void)out_size;
    const float* zi = (const float*)d_in[0];
    const float* zj = (const float*)d_in[1];
    float* out = (float*)d_out;

    cudaFuncSetAttribute((const void*)k_gemm_lse,
                         cudaFuncAttributeMaxDynamicSharedMemorySize, SMEM_BYTES);

    k_norm_pos<<<HALF_N / 8, 256>>>(zi, zj);
    k_gemm_lse<<<dim3(CS, NROWS / TM), 256, SMEM_BYTES>>>();
    k_finalize<<<1, 256>>>(out);
}